// round 2
// baseline (speedup 1.0000x reference)
#include <cuda_runtime.h>
#include <cstddef>

// ---------------- problem constants ----------------
#define MAX_E 16000
#define MAX_N 2000
// CH = 256, HID = 256, 3CH = 768, HEADS = 4, dk = 64

// ---------------- scratch (static device globals; no runtime alloc) --------
__device__ float g_enorm[MAX_E * 768];                       // normalized+relu edge input
__device__ float g_h1[MAX_E * 256];                          // edge hidden
__device__ float g_k[MAX_E * 256];
__device__ float g_v[MAX_E * 256];
__device__ float g_q[MAX_N * 256];
__device__ float g_attbuf[MAX_N * 256 + MAX_N * 4 + 256];    // gatt | expsum | vsum
__device__ float g_cat[MAX_N * 512];                         // [xa | g_o]
__device__ float g_h2[MAX_N * 256];

// ---------------- helpers ----------------
__global__ void zero_kernel(float* __restrict__ a, int n) {
    for (int i = blockIdx.x * blockDim.x + threadIdx.x; i < n; i += gridDim.x * blockDim.x)
        a[i] = 0.f;
}

// GroupNorm(768ch, 32 groups of 24) + ReLU over concat(x[row], x[col], edge_attr).
// One block (256 threads) per edge.
__global__ void gn_edge_in_kernel(const float* __restrict__ x, const int* __restrict__ ei,
                                  const float* __restrict__ ea,
                                  const float* __restrict__ gamma, const float* __restrict__ beta,
                                  float* __restrict__ out, int E) {
    __shared__ float buf[768];
    __shared__ float s_mu[32], s_rs[32];
    int e = blockIdx.x;
    int t = threadIdx.x;
    int r = ei[e];
    int c = ei[E + e];
    buf[t]       = x[(size_t)r * 256 + t];
    buf[256 + t] = x[(size_t)c * 256 + t];
    buf[512 + t] = ea[(size_t)e * 256 + t];
    __syncthreads();
    if (t < 32) {
        float s = 0.f, s2 = 0.f;
        #pragma unroll
        for (int i = 0; i < 24; i++) {
            float v = buf[t * 24 + i];
            s += v; s2 += v * v;
        }
        float m = s * (1.f / 24.f);
        float var = s2 * (1.f / 24.f) - m * m;
        s_mu[t] = m;
        s_rs[t] = rsqrtf(var + 1e-5f);
    }
    __syncthreads();
    #pragma unroll
    for (int i = t; i < 768; i += 256) {
        int grp = i / 24;
        float v = (buf[i] - s_mu[grp]) * s_rs[grp] * gamma[i] + beta[i];
        out[(size_t)e * 768 + i] = fmaxf(v, 0.f);
    }
}

// GroupNorm(256ch, 32 groups of 8) + ReLU. One block per row, thread = channel.
__global__ void gn256_relu_kernel(const float* __restrict__ in, const float* __restrict__ gamma,
                                  const float* __restrict__ beta, float* __restrict__ out,
                                  int ld_out) {
    int r = blockIdx.x, t = threadIdx.x;
    float v = in[(size_t)r * 256 + t];
    float s = v, s2 = v * v;
    #pragma unroll
    for (int off = 4; off >= 1; off >>= 1) {
        s  += __shfl_xor_sync(0xffffffffu, s, off);
        s2 += __shfl_xor_sync(0xffffffffu, s2, off);
    }
    float m = s * 0.125f;
    float var = s2 * 0.125f - m * m;
    float o = (v - m) * rsqrtf(var + 1e-5f) * gamma[t] + beta[t];
    out[(size_t)r * ld_out + t] = fmaxf(o, 0.f);
}

// Generic SGEMM: C[M,Ncol] = A[M,K] @ B[K,Ncol] + bias (+ resid), C row stride ldc.
// 64x64 tile, BK=16, 256 threads, 4x4 per thread. Ncol assumed multiple of 64; M guarded.
__global__ void __launch_bounds__(256) sgemm_kernel(
    const float* __restrict__ A, const float* __restrict__ B,
    const float* __restrict__ bias, const float* __restrict__ resid,
    float* __restrict__ C, int M, int Ncol, int K, int ldc) {
    __shared__ float As[16][68];
    __shared__ float Bs[16][68];
    int tid = threadIdx.x;
    int tx = tid & 15, ty = tid >> 4;
    int rowBase = blockIdx.y * 64;
    int colBase = blockIdx.x * 64;

    float acc[4][4] = {};

    int aRow = tid >> 2;           // 0..63
    int aCol = (tid & 3) * 4;      // 0,4,8,12
    int bRow = tid >> 4;           // 0..15
    int bCol = (tid & 15) * 4;     // 0..60

    const float* Aptr = A + (size_t)(rowBase + aRow) * K + aCol;
    bool aValid = (rowBase + aRow) < M;

    for (int k0 = 0; k0 < K; k0 += 16) {
        float4 av = aValid ? *(const float4*)(Aptr + k0) : make_float4(0.f, 0.f, 0.f, 0.f);
        float4 bv = *(const float4*)(B + (size_t)(k0 + bRow) * Ncol + colBase + bCol);
        As[aCol + 0][aRow] = av.x;
        As[aCol + 1][aRow] = av.y;
        As[aCol + 2][aRow] = av.z;
        As[aCol + 3][aRow] = av.w;
        *(float4*)&Bs[bRow][bCol] = bv;
        __syncthreads();
        #pragma unroll
        for (int kk = 0; kk < 16; kk++) {
            float4 a = *(const float4*)&As[kk][ty * 4];
            float4 b = *(const float4*)&Bs[kk][tx * 4];
            float ar[4] = {a.x, a.y, a.z, a.w};
            float br[4] = {b.x, b.y, b.z, b.w};
            #pragma unroll
            for (int i = 0; i < 4; i++)
                #pragma unroll
                for (int j = 0; j < 4; j++)
                    acc[i][j] += ar[i] * br[j];
        }
        __syncthreads();
    }

    #pragma unroll
    for (int i = 0; i < 4; i++) {
        int row = rowBase + ty * 4 + i;
        if (row < M) {
            #pragma unroll
            for (int j = 0; j < 4; j++) {
                int col = colBase + tx * 4 + j;
                float val = acc[i][j] + bias[col];
                if (resid) val += resid[(size_t)row * Ncol + col];
                C[(size_t)row * ldc + col] = val;
            }
        }
    }
}

// Column sums of v [E,256] -> vsum[256]  (for empty-node softmax fallback = mean over all v)
__global__ void colsum_kernel(const float* __restrict__ v, float* __restrict__ vsum, int E) {
    int t = threadIdx.x;
    float s = 0.f;
    for (int e = blockIdx.x; e < E; e += gridDim.x)
        s += v[(size_t)e * 256 + t];
    atomicAdd(&vsum[t], s);
}

// Per-edge attention scatter: one block per edge, 256 threads (channel = h*64+d).
__global__ void attn_scatter_kernel(const float* __restrict__ q, const float* __restrict__ k,
                                    const float* __restrict__ v, const int* __restrict__ ei,
                                    float* __restrict__ expsum, float* __restrict__ gatt, int E) {
    __shared__ float wsum[8];
    __shared__ float wexp[4];
    int e = blockIdx.x;
    int t = threadIdx.x;
    int n = ei[E + e];               // target node (col)
    float p = q[(size_t)n * 256 + t] * k[(size_t)e * 256 + t];
    #pragma unroll
    for (int off = 16; off >= 1; off >>= 1)
        p += __shfl_xor_sync(0xffffffffu, p, off);
    int warp = t >> 5, lane = t & 31;
    if (lane == 0) wsum[warp] = p;
    __syncthreads();
    if (t < 4) {
        float s = (wsum[2 * t] + wsum[2 * t + 1]) * 0.125f;  // / sqrt(64)
        float w = expf(s);
        wexp[t] = w;
        atomicAdd(&expsum[n * 4 + t], w);
    }
    __syncthreads();
    float w = wexp[t >> 6];
    atomicAdd(&gatt[(size_t)n * 256 + t], w * v[(size_t)e * 256 + t]);
}

// Normalize: g = gatt/expsum, or vsum/E if node has no incident edges.
__global__ void attn_finalize_kernel(float* __restrict__ gatt, const float* __restrict__ expsum,
                                     const float* __restrict__ vsum, float invE) {
    int n = blockIdx.x, t = threadIdx.x;
    float es = expsum[n * 4 + (t >> 6)];
    float val = (es > 0.f) ? gatt[(size_t)n * 256 + t] / es : vsum[t] * invE;
    gatt[(size_t)n * 256 + t] = val;
}

// ---------------- launch ----------------
extern "C" void kernel_launch(void* const* d_in, const int* in_sizes, int n_in,
                              void* d_out, int out_size) {
    const float* x       = (const float*)d_in[0];
    const int*   ei      = (const int*)d_in[1];
    const float* ea      = (const float*)d_in[2];
    const float* gn_e1_g = (const float*)d_in[3];
    const float* gn_e1_b = (const float*)d_in[4];
    const float* We1     = (const float*)d_in[5];
    const float* be1     = (const float*)d_in[6];
    const float* gn_e2_g = (const float*)d_in[7];
    const float* gn_e2_b = (const float*)d_in[8];
    const float* We2     = (const float*)d_in[9];
    const float* be2     = (const float*)d_in[10];
    const float* gn_n_g  = (const float*)d_in[11];
    const float* gn_n_b  = (const float*)d_in[12];
    const float* Wq      = (const float*)d_in[13];
    const float* bq      = (const float*)d_in[14];
    const float* Wk      = (const float*)d_in[15];
    const float* bk      = (const float*)d_in[16];
    const float* Wv      = (const float*)d_in[17];
    const float* bv      = (const float*)d_in[18];
    const float* Wo      = (const float*)d_in[19];
    const float* bo      = (const float*)d_in[20];
    const float* Wn1     = (const float*)d_in[21];
    const float* bn1     = (const float*)d_in[22];
    const float* gn_n2_g = (const float*)d_in[23];
    const float* gn_n2_b = (const float*)d_in[24];
    const float* Wn2     = (const float*)d_in[25];
    const float* bn2     = (const float*)d_in[26];

    const int N = in_sizes[0] / 256;
    const int E = in_sizes[2] / 256;

    float *enorm, *h1, *kbuf, *vbuf, *qbuf, *attbuf, *cat, *h2;
    cudaGetSymbolAddress((void**)&enorm,  g_enorm);
    cudaGetSymbolAddress((void**)&h1,     g_h1);
    cudaGetSymbolAddress((void**)&kbuf,   g_k);
    cudaGetSymbolAddress((void**)&vbuf,   g_v);
    cudaGetSymbolAddress((void**)&qbuf,   g_q);
    cudaGetSymbolAddress((void**)&attbuf, g_attbuf);
    cudaGetSymbolAddress((void**)&cat,    g_cat);
    cudaGetSymbolAddress((void**)&h2,     g_h2);

    float* n_out = (float*)d_out;                       // [N,256]
    float* e_out = (float*)d_out + (size_t)N * 256;     // [E,256]

    float* gatt   = attbuf;
    float* expsum = attbuf + (size_t)N * 256;
    float* vsum   = expsum + (size_t)N * 4;

    dim3 gE(4, (E + 63) / 64);   // Ncol=256 -> 4 col blocks
    dim3 gN(4, (N + 63) / 64);

    // 1. zero attention accumulators (gatt, expsum, vsum contiguous)
    zero_kernel<<<256, 256>>>(attbuf, N * 256 + N * 4 + 256);
    // 2. edge input GN+ReLU (fused gather of x[row], x[col], edge_attr)
    gn_edge_in_kernel<<<E, 256>>>(x, ei, ea, gn_e1_g, gn_e1_b, enorm, E);
    // 3. h1 = enorm @ We1 + be1     [E,768]x[768,256]
    sgemm_kernel<<<gE, 256>>>(enorm, We1, be1, nullptr, h1, E, 256, 768, 256);
    // 4. GN+ReLU (in place)
    gn256_relu_kernel<<<E, 256>>>(h1, gn_e2_g, gn_e2_b, h1, 256);
    // 5. e_out = h1 @ We2 + be2 + edge_attr  -> straight into d_out
    sgemm_kernel<<<gE, 256>>>(h1, We2, be2, ea, e_out, E, 256, 256, 256);
    // 6. q = x @ Wq + bq
    sgemm_kernel<<<gN, 256>>>(x, Wq, bq, nullptr, qbuf, N, 256, 256, 256);
    // 7/8. k,v = e_out @ Wk/Wv + b
    sgemm_kernel<<<gE, 256>>>(e_out, Wk, bk, nullptr, kbuf, E, 256, 256, 256);
    sgemm_kernel<<<gE, 256>>>(e_out, Wv, bv, nullptr, vbuf, E, 256, 256, 256);
    // 9. column sums of v (fallback for edge-less nodes)
    colsum_kernel<<<64, 256>>>(vbuf, vsum, E);
    // 10. attention scatter (exp weights + weighted v accumulation)
    attn_scatter_kernel<<<E, 256>>>(qbuf, kbuf, vbuf, ei, expsum, gatt, E);
    // 11. finalize softmax normalization (+ empty-node fallback)
    attn_finalize_kernel<<<N, 256>>>(gatt, expsum, vsum, 1.0f / (float)E);
    // 12. g_o = gatt @ Wo + bo -> right half of cat buffer (ldc=512)
    sgemm_kernel<<<gN, 256>>>(gatt, Wo, bo, nullptr, cat + 256, N, 256, 256, 512);
    // 13. xa = ReLU(GN(x)) -> left half of cat buffer
    gn256_relu_kernel<<<N, 256>>>(x, gn_n_g, gn_n_b, cat, 512);
    // 14. h2 = cat @ Wn1 + bn1   [N,512]x[512,256]
    sgemm_kernel<<<gN, 256>>>(cat, Wn1, bn1, nullptr, h2, N, 256, 512, 256);
    // 15. GN+ReLU (in place)
    gn256_relu_kernel<<<N, 256>>>(h2, gn_n2_g, gn_n2_b, h2, 256);
    // 16. n_out = h2 @ Wn2 + bn2 + x
    sgemm_kernel<<<gN, 256>>>(h2, Wn2, bn2, x, n_out, N, 256, 256, 256);
}

// round 4
// speedup vs baseline: 1.0518x; 1.0518x over previous
#include <cuda_runtime.h>
#include <cuda_bf16.h>
#include <cstdint>
#include <cstddef>

// ================= problem constants =================
#define MAX_E 16000
#define MAX_N 2000
// CH=256, HID=256, 3CH=768, HEADS=4, dk=64

// ================= helpers =================
__device__ __forceinline__ uint32_t smem_to_u32(const void* smem_ptr) {
    uint32_t addr;
    asm("{ .reg .u64 tmp; cvta.to.shared.u64 tmp, %1; cvt.u32.u64 %0, tmp; }"
        : "=r"(addr) : "l"(smem_ptr));
    return addr;
}
#define SMEM_SWIZZLE_128B(byte_offset) ((byte_offset) ^ (((byte_offset) >> 3) & 0x70))

__device__ __forceinline__ void cp_async16(uint32_t dst, const void* src, bool valid) {
    int sz = valid ? 16 : 0;
    asm volatile("cp.async.cg.shared.global [%0], [%1], 16, %2;"
                 :: "r"(dst), "l"(src), "r"(sz) : "memory");
}
__device__ __forceinline__ void cp_commit() {
    asm volatile("cp.async.commit_group;" ::: "memory");
}
template <int N>
__device__ __forceinline__ void cp_wait() {
    asm volatile("cp.async.wait_group %0;" :: "n"(N) : "memory");
}
__device__ __forceinline__ uint32_t lds32(uint32_t addr) {
    uint32_t v;
    asm volatile("ld.shared.b32 %0, [%1];" : "=r"(v) : "r"(addr));
    return v;
}
__device__ __forceinline__ void mma16816(float* c, const uint32_t* a, uint32_t b0, uint32_t b1) {
    asm volatile(
        "mma.sync.aligned.m16n8k16.row.col.f32.bf16.bf16.f32 "
        "{%0,%1,%2,%3}, {%4,%5,%6,%7}, {%8,%9}, {%0,%1,%2,%3};"
        : "+f"(c[0]), "+f"(c[1]), "+f"(c[2]), "+f"(c[3])
        : "r"(a[0]), "r"(a[1]), "r"(a[2]), "r"(a[3]), "r"(b0), "r"(b1));
}

// ================= scratch (static device globals) =================
__device__ __align__(256) __nv_bfloat16 g_ein3[(size_t)MAX_E * 2304];
__device__ __align__(256) float         g_h1[(size_t)MAX_E * 256];
__device__ __align__(256) __nv_bfloat16 g_h1b3[(size_t)MAX_E * 768];
__device__ __align__(256) __nv_bfloat16 g_eoutb3[(size_t)MAX_E * 768];
__device__ __align__(256) __nv_bfloat16 g_xb3[(size_t)MAX_N * 768];
__device__ __align__(256) float         g_q[(size_t)MAX_N * 256];
__device__ __align__(256) float         g_k[(size_t)MAX_E * 256];
__device__ __align__(256) float         g_v[(size_t)MAX_E * 256];
__device__ __align__(256) float         g_attbuf[(size_t)MAX_N * 256 + MAX_N * 4 + 256];
__device__ __align__(256) __nv_bfloat16 g_gattb3[(size_t)MAX_N * 768];
__device__ __align__(256) __nv_bfloat16 g_cat3[(size_t)MAX_N * 1536];
__device__ __align__(256) float         g_h2[(size_t)MAX_N * 256];
__device__ __align__(256) __nv_bfloat16 g_h2b3[(size_t)MAX_N * 768];
// transposed 3-seg weights [256, 3K], segments [hi | lo | hi]
__device__ __align__(256) __nv_bfloat16 g_We1t3[256 * 2304];
__device__ __align__(256) __nv_bfloat16 g_We2t3[256 * 768];
__device__ __align__(256) __nv_bfloat16 g_Wqt3[256 * 768];
__device__ __align__(256) __nv_bfloat16 g_Wkt3[256 * 768];
__device__ __align__(256) __nv_bfloat16 g_Wvt3[256 * 768];
__device__ __align__(256) __nv_bfloat16 g_Wot3[256 * 768];
__device__ __align__(256) __nv_bfloat16 g_Wn1t3[256 * 1536];
__device__ __align__(256) __nv_bfloat16 g_Wn2t3[256 * 768];

// ================= small kernels =================
__global__ void zero_kernel(float* __restrict__ a, int n) {
    for (int i = blockIdx.x * blockDim.x + threadIdx.x; i < n; i += gridDim.x * blockDim.x)
        a[i] = 0.f;
}

__device__ __forceinline__ void split_bf16(float v, __nv_bfloat16& h, __nv_bfloat16& l) {
    h = __float2bfloat16(v);
    l = __float2bfloat16(v - __bfloat162float(h));
}

__global__ void wprep_kernel(const float* __restrict__ W, __nv_bfloat16* __restrict__ Wt3, int K) {
    int idx = blockIdx.x * blockDim.x + threadIdx.x;
    if (idx >= K * 256) return;
    int k = idx >> 8, n = idx & 255;
    float v = W[(size_t)k * 256 + n];
    __nv_bfloat16 h, l; split_bf16(v, h, l);
    size_t base = (size_t)n * 3 * K;
    Wt3[base + k] = h;
    Wt3[base + K + k] = l;
    Wt3[base + 2 * K + k] = h;
}

__global__ void xprep_kernel(const float* __restrict__ x, __nv_bfloat16* __restrict__ out, int M) {
    int idx = blockIdx.x * blockDim.x + threadIdx.x;
    if (idx >= M * 256) return;
    int r = idx >> 8, c = idx & 255;
    float v = x[idx];
    __nv_bfloat16 h, l; split_bf16(v, h, l);
    size_t base = (size_t)r * 768;
    out[base + c] = h;
    out[base + 256 + c] = h;
    out[base + 512 + c] = l;
}

// GN(768ch, 32 groups of 24)+ReLU over concat(x[row],x[col],ea) -> bf16 3-seg [E,2304]
__global__ void gn_edge3_kernel(const float* __restrict__ x, const int* __restrict__ ei,
                                const float* __restrict__ ea,
                                const float* __restrict__ gamma, const float* __restrict__ beta,
                                __nv_bfloat16* __restrict__ out, int E) {
    __shared__ float buf[768];
    __shared__ float s_mu[32], s_rs[32];
    int e = blockIdx.x;
    int t = threadIdx.x;
    int r = ei[e];
    int c = ei[E + e];
    buf[t]       = x[(size_t)r * 256 + t];
    buf[256 + t] = x[(size_t)c * 256 + t];
    buf[512 + t] = ea[(size_t)e * 256 + t];
    __syncthreads();
    if (t < 32) {
        float s = 0.f, s2 = 0.f;
        #pragma unroll
        for (int i = 0; i < 24; i++) { float v = buf[t * 24 + i]; s += v; s2 += v * v; }
        float m = s * (1.f / 24.f);
        float var = s2 * (1.f / 24.f) - m * m;
        s_mu[t] = m; s_rs[t] = rsqrtf(var + 1e-5f);
    }
    __syncthreads();
    size_t base = (size_t)e * 2304;
    #pragma unroll
    for (int i = t; i < 768; i += 256) {
        int grp = i / 24;
        float v = fmaxf((buf[i] - s_mu[grp]) * s_rs[grp] * gamma[i] + beta[i], 0.f);
        __nv_bfloat16 h, l; split_bf16(v, h, l);
        out[base + i] = h;
        out[base + 768 + i] = h;
        out[base + 1536 + i] = l;
    }
}

// GN(256, groups of 8)+ReLU, thread-per-group; bf16 3-seg output
__global__ void gn256b_kernel(const float* __restrict__ in, const float* __restrict__ gamma,
                              const float* __restrict__ beta, __nv_bfloat16* __restrict__ out,
                              int bld, int bofs, int bseg, int M) {
    int t = threadIdx.x;
    int row = blockIdx.x * 8 + (t >> 5);
    if (row >= M) return;
    int g = t & 31;
    const float* p = in + (size_t)row * 256 + g * 8;
    float4 a = *(const float4*)p;
    float4 b = *(const float4*)(p + 4);
    float s = a.x + a.y + a.z + a.w + b.x + b.y + b.z + b.w;
    float s2 = a.x*a.x + a.y*a.y + a.z*a.z + a.w*a.w + b.x*b.x + b.y*b.y + b.z*b.z + b.w*b.w;
    float m = s * 0.125f;
    float var = s2 * 0.125f - m * m;
    float rs = rsqrtf(var + 1e-5f);
    float vals[8] = {a.x, a.y, a.z, a.w, b.x, b.y, b.z, b.w};
    __nv_bfloat16 hs[8], ls[8];
    #pragma unroll
    for (int i = 0; i < 8; i++) {
        int ch = g * 8 + i;
        float v = fmaxf((vals[i] - m) * rs * gamma[ch] + beta[ch], 0.f);
        split_bf16(v, hs[i], ls[i]);
    }
    __nv_bfloat16* o = out + (size_t)row * bld + bofs + g * 8;
    #pragma unroll
    for (int i = 0; i < 4; i++) {
        __nv_bfloat162 hp = __halves2bfloat162(hs[2*i], hs[2*i+1]);
        __nv_bfloat162 lp = __halves2bfloat162(ls[2*i], ls[2*i+1]);
        *(__nv_bfloat162*)(o + 2*i) = hp;
        *(__nv_bfloat162*)(o + bseg + 2*i) = hp;
        *(__nv_bfloat162*)(o + 2*bseg + 2*i) = lp;
    }
}

__global__ void colsum_kernel(const float* __restrict__ v, float* __restrict__ vsum, int E) {
    int t = threadIdx.x;
    float s = 0.f;
    for (int e = blockIdx.x; e < E; e += gridDim.x)
        s += v[(size_t)e * 256 + t];
    atomicAdd(&vsum[t], s);
}

__global__ void attn_scatter_kernel(const float* __restrict__ q, const float* __restrict__ k,
                                    const float* __restrict__ v, const int* __restrict__ ei,
                                    float* __restrict__ expsum, float* __restrict__ gatt, int E) {
    __shared__ float wsum[8];
    __shared__ float wexp[4];
    int e = blockIdx.x;
    int t = threadIdx.x;
    int n = ei[E + e];
    float p = q[(size_t)n * 256 + t] * k[(size_t)e * 256 + t];
    #pragma unroll
    for (int off = 16; off >= 1; off >>= 1)
        p += __shfl_xor_sync(0xffffffffu, p, off);
    int warp = t >> 5, lane = t & 31;
    if (lane == 0) wsum[warp] = p;
    __syncthreads();
    if (t < 4) {
        float s = (wsum[2 * t] + wsum[2 * t + 1]) * 0.125f;
        float w = expf(s);
        wexp[t] = w;
        atomicAdd(&expsum[n * 4 + t], w);
    }
    __syncthreads();
    float w = wexp[t >> 6];
    atomicAdd(&gatt[(size_t)n * 256 + t], w * v[(size_t)e * 256 + t]);
}

__global__ void attn_finalize3_kernel(const float* __restrict__ gatt, const float* __restrict__ expsum,
                                      const float* __restrict__ vsum, float invE,
                                      __nv_bfloat16* __restrict__ out) {
    int n = blockIdx.x, t = threadIdx.x;
    float es = expsum[n * 4 + (t >> 6)];
    float val = (es > 0.f) ? gatt[(size_t)n * 256 + t] / es : vsum[t] * invE;
    __nv_bfloat16 h, l; split_bf16(val, h, l);
    size_t base = (size_t)n * 768;
    out[base + t] = h;
    out[base + 256 + t] = h;
    out[base + 512 + t] = l;
}

// ================= mma.sync GEMM =================
// C[M,256] = A3[M,lda](bf16) @ B3[256,lda]^T + bias (+resid)
// CTA: 128 rows x 256 cols. K chunks of 64 bf16 (128B SW128 rows), cp.async double buffered.
// 8 warps, each 64x64 warp tile via mma.sync m16n8k16 bf16.
__global__ void __launch_bounds__(256, 1) tc_gemm_kernel(
    const __nv_bfloat16* __restrict__ A3, int lda,
    const __nv_bfloat16* __restrict__ B3,
    const float* __restrict__ bias,
    const float* __restrict__ resid,
    float* __restrict__ Cf, int ldc,
    __nv_bfloat16* __restrict__ Cb, int bld, int bofs, int bseg,
    int M)
{
    extern __shared__ char smem_raw[];
    char* smem = (char*)(((uintptr_t)smem_raw + 1023) & ~(uintptr_t)1023);
    uint32_t sbase = smem_to_u32(smem);

    int tid = threadIdx.x;
    int wid = tid >> 5;
    int lane = tid & 31;
    int g = lane >> 2, tg = lane & 3;
    int wm = (wid >> 2) * 64;
    int wn = (wid & 3) * 64;

    int rowBase = blockIdx.x * 128;
    int NC = lda / 64;

    // loaders: A thread t -> row t/2, uint4 group (t&1)*4..; B thread t -> row t (256 rows)
    int ar = tid >> 1;
    int au = (tid & 1) * 4;
    bool avalid = (rowBase + ar) < M;
    const char* Arow = (const char*)(A3 + (size_t)(rowBase + ar) * lda);
    const char* Brow = (const char*)(B3 + (size_t)tid * lda);

    auto load_chunk = [&](int c, int bb) {
        uint32_t pA = sbase + bb * 16384;
        uint32_t pB = sbase + 32768 + bb * 32768;
        #pragma unroll
        for (int j = 0; j < 4; j++)
            cp_async16(pA + SMEM_SWIZZLE_128B(ar * 128 + (au + j) * 16),
                       Arow + (size_t)c * 128 + (au + j) * 16, avalid);
        #pragma unroll
        for (int j = 0; j < 8; j++)
            cp_async16(pB + SMEM_SWIZZLE_128B(tid * 128 + j * 16),
                       Brow + (size_t)c * 128 + j * 16, true);
    };

    float acc[4][8][4];
    #pragma unroll
    for (int mt = 0; mt < 4; mt++)
        #pragma unroll
        for (int nt = 0; nt < 8; nt++)
            #pragma unroll
            for (int i = 0; i < 4; i++) acc[mt][nt][i] = 0.f;

    load_chunk(0, 0); cp_commit();
    if (NC > 1) { load_chunk(1, 1); cp_commit(); }
    cp_wait<1>();
    __syncthreads();

    for (int c = 0; c < NC; c++) {
        int bb = c & 1;
        uint32_t aBase = sbase + bb * 16384 + (uint32_t)(wm + g) * 128;
        uint32_t bBase = sbase + 32768 + bb * 32768 + (uint32_t)(wn + g) * 128;
        uint32_t gx = (uint32_t)(g << 4);
        #pragma unroll
        for (int ks = 0; ks < 4; ks++) {
            uint32_t x  = (uint32_t)(ks * 32 + tg * 4) ^ gx;
            uint32_t x2 = (uint32_t)(ks * 32 + tg * 4 + 16) ^ gx;
            uint32_t a[4][4];
            #pragma unroll
            for (int mt = 0; mt < 4; mt++) {
                uint32_t rb = aBase + mt * 2048;
                a[mt][0] = lds32(rb + x);
                a[mt][1] = lds32(rb + 1024 + x);
                a[mt][2] = lds32(rb + x2);
                a[mt][3] = lds32(rb + 1024 + x2);
            }
            #pragma unroll
            for (int nt = 0; nt < 8; nt++) {
                uint32_t rb = bBase + nt * 1024;
                uint32_t b0 = lds32(rb + x);
                uint32_t b1 = lds32(rb + x2);
                #pragma unroll
                for (int mt = 0; mt < 4; mt++)
                    mma16816(acc[mt][nt], a[mt], b0, b1);
            }
        }
        __syncthreads();
        if (c + 2 < NC) {
            load_chunk(c + 2, bb); cp_commit();
            cp_wait<1>();
        } else {
            cp_wait<0>();
        }
        __syncthreads();
    }

    // epilogue
    #pragma unroll
    for (int mt = 0; mt < 4; mt++) {
        #pragma unroll
        for (int half = 0; half < 2; half++) {
            int row = rowBase + wm + mt * 16 + g + half * 8;
            if (row >= M) continue;
            #pragma unroll
            for (int nt = 0; nt < 8; nt++) {
                int col = wn + nt * 8 + tg * 2;
                float v0 = acc[mt][nt][half * 2 + 0];
                float v1 = acc[mt][nt][half * 2 + 1];
                float2 bv = *(const float2*)(bias + col);
                v0 += bv.x; v1 += bv.y;
                if (resid) {
                    float2 rv = *(const float2*)(resid + (size_t)row * 256 + col);
                    v0 += rv.x; v1 += rv.y;
                }
                if (Cf)
                    *(float2*)(Cf + (size_t)row * ldc + col) = make_float2(v0, v1);
                if (Cb) {
                    __nv_bfloat16 h0, l0, h1x, l1x;
                    split_bf16(v0, h0, l0); split_bf16(v1, h1x, l1x);
                    __nv_bfloat162 hp = __halves2bfloat162(h0, h1x);
                    __nv_bfloat162 lp = __halves2bfloat162(l0, l1x);
                    __nv_bfloat16* o = Cb + (size_t)row * bld + bofs + col;
                    *(__nv_bfloat162*)(o) = hp;
                    *(__nv_bfloat162*)(o + bseg) = hp;
                    *(__nv_bfloat162*)(o + 2 * bseg) = lp;
                }
            }
        }
    }
}

// ================= launch =================
extern "C" void kernel_launch(void* const* d_in, const int* in_sizes, int n_in,
                              void* d_out, int out_size) {
    const float* x       = (const float*)d_in[0];
    const int*   ei      = (const int*)d_in[1];
    const float* ea      = (const float*)d_in[2];
    const float* gn_e1_g = (const float*)d_in[3];
    const float* gn_e1_b = (const float*)d_in[4];
    const float* We1     = (const float*)d_in[5];
    const float* be1     = (const float*)d_in[6];
    const float* gn_e2_g = (const float*)d_in[7];
    const float* gn_e2_b = (const float*)d_in[8];
    const float* We2     = (const float*)d_in[9];
    const float* be2     = (const float*)d_in[10];
    const float* gn_n_g  = (const float*)d_in[11];
    const float* gn_n_b  = (const float*)d_in[12];
    const float* Wq      = (const float*)d_in[13];
    const float* bq      = (const float*)d_in[14];
    const float* Wk      = (const float*)d_in[15];
    const float* bk      = (const float*)d_in[16];
    const float* Wv      = (const float*)d_in[17];
    const float* bv      = (const float*)d_in[18];
    const float* Wo      = (const float*)d_in[19];
    const float* bo      = (const float*)d_in[20];
    const float* Wn1     = (const float*)d_in[21];
    const float* bn1     = (const float*)d_in[22];
    const float* gn_n2_g = (const float*)d_in[23];
    const float* gn_n2_b = (const float*)d_in[24];
    const float* Wn2     = (const float*)d_in[25];
    const float* bn2     = (const float*)d_in[26];

    const int N = in_sizes[0] / 256;
    const int E = in_sizes[2] / 256;

    __nv_bfloat16 *ein3, *h1b3, *eoutb3, *xb3, *gattb3, *cat3, *h2b3;
    __nv_bfloat16 *We1t3, *We2t3, *Wqt3, *Wkt3, *Wvt3, *Wot3, *Wn1t3, *Wn2t3;
    float *h1, *qb, *kb, *vb, *attbuf, *h2;
    cudaGetSymbolAddress((void**)&ein3,   g_ein3);
    cudaGetSymbolAddress((void**)&h1,     g_h1);
    cudaGetSymbolAddress((void**)&h1b3,   g_h1b3);
    cudaGetSymbolAddress((void**)&eoutb3, g_eoutb3);
    cudaGetSymbolAddress((void**)&xb3,    g_xb3);
    cudaGetSymbolAddress((void**)&qb,     g_q);
    cudaGetSymbolAddress((void**)&kb,     g_k);
    cudaGetSymbolAddress((void**)&vb,     g_v);
    cudaGetSymbolAddress((void**)&attbuf, g_attbuf);
    cudaGetSymbolAddress((void**)&gattb3, g_gattb3);
    cudaGetSymbolAddress((void**)&cat3,   g_cat3);
    cudaGetSymbolAddress((void**)&h2,     g_h2);
    cudaGetSymbolAddress((void**)&h2b3,   g_h2b3);
    cudaGetSymbolAddress((void**)&We1t3,  g_We1t3);
    cudaGetSymbolAddress((void**)&We2t3,  g_We2t3);
    cudaGetSymbolAddress((void**)&Wqt3,   g_Wqt3);
    cudaGetSymbolAddress((void**)&Wkt3,   g_Wkt3);
    cudaGetSymbolAddress((void**)&Wvt3,   g_Wvt3);
    cudaGetSymbolAddress((void**)&Wot3,   g_Wot3);
    cudaGetSymbolAddress((void**)&Wn1t3,  g_Wn1t3);
    cudaGetSymbolAddress((void**)&Wn2t3,  g_Wn2t3);

    float* n_out = (float*)d_out;
    float* e_out = (float*)d_out + (size_t)N * 256;
    float* gatt   = attbuf;
    float* expsum = attbuf + (size_t)N * 256;
    float* vsum   = expsum + (size_t)N * 4;

    const int DSMEM = 98304 + 1024;
    cudaFuncSetAttribute(tc_gemm_kernel, cudaFuncAttributeMaxDynamicSharedMemorySize, DSMEM);

    int gemmE = (E + 127) / 128;
    int gemmN = (N + 127) / 128;

    // --- prep ---
    wprep_kernel<<<(768 * 256 + 255) / 256, 256>>>(We1, We1t3, 768);
    wprep_kernel<<<(256 * 256 + 255) / 256, 256>>>(We2, We2t3, 256);
    wprep_kernel<<<(256 * 256 + 255) / 256, 256>>>(Wq,  Wqt3,  256);
    wprep_kernel<<<(256 * 256 + 255) / 256, 256>>>(Wk,  Wkt3,  256);
    wprep_kernel<<<(256 * 256 + 255) / 256, 256>>>(Wv,  Wvt3,  256);
    wprep_kernel<<<(256 * 256 + 255) / 256, 256>>>(Wo,  Wot3,  256);
    wprep_kernel<<<(512 * 256 + 255) / 256, 256>>>(Wn1, Wn1t3, 512);
    wprep_kernel<<<(256 * 256 + 255) / 256, 256>>>(Wn2, Wn2t3, 256);
    xprep_kernel<<<(N * 256 + 255) / 256, 256>>>(x, xb3, N);
    zero_kernel<<<256, 256>>>(attbuf, N * 256 + N * 4 + 256);

    // --- edge model ---
    gn_edge3_kernel<<<E, 256>>>(x, ei, ea, gn_e1_g, gn_e1_b, ein3, E);
    tc_gemm_kernel<<<gemmE, 256, DSMEM>>>(ein3, 2304, We1t3, be1, nullptr,
                                          h1, 256, nullptr, 0, 0, 0, E);
    gn256b_kernel<<<(E + 7) / 8, 256>>>(h1, gn_e2_g, gn_e2_b, h1b3, 768, 0, 256, E);
    tc_gemm_kernel<<<gemmE, 256, DSMEM>>>(h1b3, 768, We2t3, be2, ea,
                                          e_out, 256, eoutb3, 768, 0, 256, E);

    // --- attention projections ---
    tc_gemm_kernel<<<gemmN, 256, DSMEM>>>(xb3, 768, Wqt3, bq, nullptr,
                                          qb, 256, nullptr, 0, 0, 0, N);
    tc_gemm_kernel<<<gemmE, 256, DSMEM>>>(eoutb3, 768, Wkt3, bk, nullptr,
                                          kb, 256, nullptr, 0, 0, 0, E);
    tc_gemm_kernel<<<gemmE, 256, DSMEM>>>(eoutb3, 768, Wvt3, bv, nullptr,
                                          vb, 256, nullptr, 0, 0, 0, E);

    // --- sparse attention ---
    colsum_kernel<<<64, 256>>>(vb, vsum, E);
    attn_scatter_kernel<<<E, 256>>>(qb, kb, vb, ei, expsum, gatt, E);
    attn_finalize3_kernel<<<N, 256>>>(gatt, expsum, vsum, 1.0f / (float)E, gattb3);

    // --- node model ---
    tc_gemm_kernel<<<gemmN, 256, DSMEM>>>(gattb3, 768, Wot3, bo, nullptr,
                                          nullptr, 0, cat3, 1536, 256, 512, N);
    gn256b_kernel<<<(N + 7) / 8, 256>>>(x, gn_n_g, gn_n_b, cat3, 1536, 0, 512, N);
    tc_gemm_kernel<<<gemmN, 256, DSMEM>>>(cat3, 1536, Wn1t3, bn1, nullptr,
                                          h2, 256, nullptr, 0, 0, 0, N);
    gn256b_kernel<<<(N + 7) / 8, 256>>>(h2, gn_n2_g, gn_n2_b, h2b3, 768, 0, 256, N);
    tc_gemm_kernel<<<gemmN, 256, DSMEM>>>(h2b3, 768, Wn2t3, bn2, x,
                                          n_out, 256, nullptr, 0, 0, 0, N);
}

// round 5
// speedup vs baseline: 1.0838x; 1.0304x over previous
#include <cuda_runtime.h>
#include <cuda_bf16.h>
#include <cstdint>
#include <cstddef>

// ================= problem constants =================
#define MAX_E 16000
#define MAX_N 2000
// CH=256, HID=256, 3CH=768, HEADS=4, dk=64

// ================= helpers =================
__device__ __forceinline__ uint32_t smem_to_u32(const void* smem_ptr) {
    uint32_t addr;
    asm("{ .reg .u64 tmp; cvta.to.shared.u64 tmp, %1; cvt.u32.u64 %0, tmp; }"
        : "=r"(addr) : "l"(smem_ptr));
    return addr;
}
#define SMEM_SWIZZLE_128B(byte_offset) ((byte_offset) ^ (((byte_offset) >> 3) & 0x70))

__device__ __forceinline__ void cp_async16(uint32_t dst, const void* src, bool valid) {
    int sz = valid ? 16 : 0;
    asm volatile("cp.async.cg.shared.global [%0], [%1], 16, %2;"
                 :: "r"(dst), "l"(src), "r"(sz) : "memory");
}
__device__ __forceinline__ void cp_commit() {
    asm volatile("cp.async.commit_group;" ::: "memory");
}
template <int N>
__device__ __forceinline__ void cp_wait() {
    asm volatile("cp.async.wait_group %0;" :: "n"(N) : "memory");
}
__device__ __forceinline__ void ldsm4(uint32_t& r0, uint32_t& r1, uint32_t& r2, uint32_t& r3,
                                      uint32_t addr) {
    asm volatile("ldmatrix.sync.aligned.m8n8.x4.shared.b16 {%0,%1,%2,%3}, [%4];"
                 : "=r"(r0), "=r"(r1), "=r"(r2), "=r"(r3) : "r"(addr));
}
__device__ __forceinline__ void mma16816(float* c, const uint32_t* a, uint32_t b0, uint32_t b1) {
    asm volatile(
        "mma.sync.aligned.m16n8k16.row.col.f32.bf16.bf16.f32 "
        "{%0,%1,%2,%3}, {%4,%5,%6,%7}, {%8,%9}, {%0,%1,%2,%3};"
        : "+f"(c[0]), "+f"(c[1]), "+f"(c[2]), "+f"(c[3])
        : "r"(a[0]), "r"(a[1]), "r"(a[2]), "r"(a[3]), "r"(b0), "r"(b1));
}
__device__ __forceinline__ void split_bf16(float v, __nv_bfloat16& h, __nv_bfloat16& l) {
    h = __float2bfloat16(v);
    l = __float2bfloat16(v - __bfloat162float(h));
}

// ================= scratch =================
// 2-seg bf16 activations [hi | lo], physical row = 2K
__device__ __align__(256) __nv_bfloat16 g_ein2[(size_t)MAX_E * 1536];
__device__ __align__(256) float         g_h1[(size_t)MAX_E * 256];
__device__ __align__(256) __nv_bfloat16 g_h1b[(size_t)MAX_E * 512];
__device__ __align__(256) __nv_bfloat16 g_eoutb[(size_t)MAX_E * 512];
__device__ __align__(256) __nv_bfloat16 g_xb[(size_t)MAX_N * 512];
__device__ __align__(256) float         g_q[(size_t)MAX_N * 256];
__device__ __align__(256) float         g_kv[(size_t)MAX_E * 512];
__device__ __align__(256) float         g_attbuf[(size_t)MAX_N * 256 + MAX_N * 4 + 256];
__device__ __align__(256) __nv_bfloat16 g_gattb[(size_t)MAX_N * 512];
__device__ __align__(256) __nv_bfloat16 g_cat2[(size_t)MAX_N * 1024];
__device__ __align__(256) float         g_h2[(size_t)MAX_N * 256];
__device__ __align__(256) __nv_bfloat16 g_h2b[(size_t)MAX_N * 512];
__device__ __align__(256) float         g_bkv[512];
// 2-seg transposed weights [Ncols, 2K] = [hi | lo]
__device__ __align__(256) __nv_bfloat16 g_We1t[256 * 1536];
__device__ __align__(256) __nv_bfloat16 g_We2t[256 * 512];
__device__ __align__(256) __nv_bfloat16 g_Wqt[256 * 512];
__device__ __align__(256) __nv_bfloat16 g_Wkvt[512 * 512];   // rows 0-255 = Wk, 256-511 = Wv
__device__ __align__(256) __nv_bfloat16 g_Wot[256 * 512];
__device__ __align__(256) __nv_bfloat16 g_Wn1t[256 * 1024];
__device__ __align__(256) __nv_bfloat16 g_Wn2t[256 * 512];

// ================= fused prep =================
struct WPA {
    const float* W[8];
    __nv_bfloat16* O[8];
    int K[8];
    int start[9];
};
// one block per (weight, k-row); 256 threads = output cols
__global__ void wprep_all_kernel(WPA a) {
    int b = blockIdx.x;
    int i = 0;
    #pragma unroll
    for (int j = 1; j < 8; j++) if (b >= a.start[j]) i = j;
    int k = b - a.start[i];
    int K = a.K[i];
    int col = threadIdx.x;
    float v = a.W[i][(size_t)k * 256 + col];
    __nv_bfloat16 h, l; split_bf16(v, h, l);
    a.O[i][(size_t)col * 2 * K + k] = h;
    a.O[i][(size_t)col * 2 * K + K + k] = l;
}

// xprep (2-seg) + zero attbuf + build bkv
__global__ void misc_prep_kernel(const float* __restrict__ x, __nv_bfloat16* __restrict__ xb,
                                 float* __restrict__ attbuf, int zcount,
                                 const float* __restrict__ bk, const float* __restrict__ bv,
                                 float* __restrict__ bkv, int M) {
    int idx = blockIdx.x * blockDim.x + threadIdx.x;
    if (idx < M * 256) {
        int r = idx >> 8, c = idx & 255;
        float v = x[idx];
        __nv_bfloat16 h, l; split_bf16(v, h, l);
        xb[(size_t)r * 512 + c] = h;
        xb[(size_t)r * 512 + 256 + c] = l;
    }
    int z = idx - M * 256;
    if (z >= 0 && z < zcount) attbuf[z] = 0.f;
    int bidx = idx - M * 256 - zcount;
    if (bidx >= 0 && bidx < 512)
        bkv[bidx] = (bidx < 256) ? bk[bidx] : bv[bidx - 256];
}

// GN(768, 32 groups of 24)+ReLU over concat(x[row],x[col],ea) -> 2-seg [E,1536]
__global__ void gn_edge2_kernel(const float* __restrict__ x, const int* __restrict__ ei,
                                const float* __restrict__ ea,
                                const float* __restrict__ gamma, const float* __restrict__ beta,
                                __nv_bfloat16* __restrict__ out, int E) {
    __shared__ float buf[768];
    __shared__ float s_mu[32], s_rs[32];
    int e = blockIdx.x;
    int t = threadIdx.x;
    int r = ei[e];
    int c = ei[E + e];
    buf[t]       = x[(size_t)r * 256 + t];
    buf[256 + t] = x[(size_t)c * 256 + t];
    buf[512 + t] = ea[(size_t)e * 256 + t];
    __syncthreads();
    if (t < 32) {
        float s = 0.f, s2 = 0.f;
        #pragma unroll
        for (int i = 0; i < 24; i++) { float v = buf[t * 24 + i]; s += v; s2 += v * v; }
        float m = s * (1.f / 24.f);
        float var = s2 * (1.f / 24.f) - m * m;
        s_mu[t] = m; s_rs[t] = rsqrtf(var + 1e-5f);
    }
    __syncthreads();
    size_t base = (size_t)e * 1536;
    #pragma unroll
    for (int i = t; i < 768; i += 256) {
        int grp = i / 24;
        float v = fmaxf((buf[i] - s_mu[grp]) * s_rs[grp] * gamma[i] + beta[i], 0.f);
        __nv_bfloat16 h, l; split_bf16(v, h, l);
        out[base + i] = h;
        out[base + 768 + i] = l;
    }
}

// GN(256, groups of 8)+ReLU, thread-per-group; 2-seg bf16 out
__global__ void gn256b_kernel(const float* __restrict__ in, const float* __restrict__ gamma,
                              const float* __restrict__ beta, __nv_bfloat16* __restrict__ out,
                              int bld, int bofs, int bseg, int M) {
    int t = threadIdx.x;
    int row = blockIdx.x * 8 + (t >> 5);
    if (row >= M) return;
    int g = t & 31;
    const float* p = in + (size_t)row * 256 + g * 8;
    float4 a = *(const float4*)p;
    float4 b = *(const float4*)(p + 4);
    float s = a.x + a.y + a.z + a.w + b.x + b.y + b.z + b.w;
    float s2 = a.x*a.x + a.y*a.y + a.z*a.z + a.w*a.w + b.x*b.x + b.y*b.y + b.z*b.z + b.w*b.w;
    float m = s * 0.125f;
    float var = s2 * 0.125f - m * m;
    float rs = rsqrtf(var + 1e-5f);
    float vals[8] = {a.x, a.y, a.z, a.w, b.x, b.y, b.z, b.w};
    __nv_bfloat16 hs[8], ls[8];
    #pragma unroll
    for (int i = 0; i < 8; i++) {
        int ch = g * 8 + i;
        float v = fmaxf((vals[i] - m) * rs * gamma[ch] + beta[ch], 0.f);
        split_bf16(v, hs[i], ls[i]);
    }
    __nv_bfloat16* o = out + (size_t)row * bld + bofs + g * 8;
    #pragma unroll
    for (int i = 0; i < 4; i++) {
        *(__nv_bfloat162*)(o + 2*i) = __halves2bfloat162(hs[2*i], hs[2*i+1]);
        *(__nv_bfloat162*)(o + bseg + 2*i) = __halves2bfloat162(ls[2*i], ls[2*i+1]);
    }
}

__global__ void colsum_kernel(const float* __restrict__ kv, float* __restrict__ vsum, int E) {
    int t = threadIdx.x;
    float s = 0.f;
    for (int e = blockIdx.x; e < E; e += gridDim.x)
        s += kv[(size_t)e * 512 + 256 + t];
    atomicAdd(&vsum[t], s);
}

__global__ void attn_scatter_kernel(const float* __restrict__ q, const float* __restrict__ kv,
                                    const int* __restrict__ ei,
                                    float* __restrict__ expsum, float* __restrict__ gatt, int E) {
    __shared__ float wsum[8];
    __shared__ float wexp[4];
    int e = blockIdx.x;
    int t = threadIdx.x;
    int n = ei[E + e];
    float p = q[(size_t)n * 256 + t] * kv[(size_t)e * 512 + t];
    #pragma unroll
    for (int off = 16; off >= 1; off >>= 1)
        p += __shfl_xor_sync(0xffffffffu, p, off);
    int warp = t >> 5, lane = t & 31;
    if (lane == 0) wsum[warp] = p;
    __syncthreads();
    if (t < 4) {
        float s = (wsum[2 * t] + wsum[2 * t + 1]) * 0.125f;
        float w = expf(s);
        wexp[t] = w;
        atomicAdd(&expsum[n * 4 + t], w);
    }
    __syncthreads();
    float w = wexp[t >> 6];
    atomicAdd(&gatt[(size_t)n * 256 + t], w * kv[(size_t)e * 512 + 256 + t]);
}

__global__ void attn_finalize2_kernel(const float* __restrict__ gatt, const float* __restrict__ expsum,
                                      const float* __restrict__ vsum, float invE,
                                      __nv_bfloat16* __restrict__ out) {
    int n = blockIdx.x, t = threadIdx.x;
    float es = expsum[n * 4 + (t >> 6)];
    float val = (es > 0.f) ? gatt[(size_t)n * 256 + t] / es : vsum[t] * invE;
    __nv_bfloat16 h, l; split_bf16(val, h, l);
    size_t base = (size_t)n * 512;
    out[base + t] = h;
    out[base + 256 + t] = l;
}

// ================= mma.sync GEMM =================
// Logical: C[M, 256*gridDim.y] = A(3-term split) @ B^T + bias (+resid)
// A physical [M, 2K] = [hi|lo]; logical chunks c in [0,3KC): map c<KC?c:c-KC -> [hi|hi|lo]
// B physical [Ncols, 2K] = [hi|lo]; map c<2KC?c:c-2KC -> [hi|lo|hi]
// => result = Ah*Wh + Ah*Wl + Al*Wh
__global__ void __launch_bounds__(256) tc_gemm_kernel(
    const __nv_bfloat16* __restrict__ A2, int lda2, int KC,
    const __nv_bfloat16* __restrict__ B2,
    const float* __restrict__ bias,
    const float* __restrict__ resid,
    float* __restrict__ Cf, int ldc,
    __nv_bfloat16* __restrict__ Cb, int bld, int bofs, int bseg,
    int M)
{
    extern __shared__ char smem_raw[];
    char* smem = (char*)(((uintptr_t)smem_raw + 1023) & ~(uintptr_t)1023);
    uint32_t sbase = smem_to_u32(smem);

    int tid = threadIdx.x;
    int wid = tid >> 5;
    int lane = tid & 31;
    int g = lane >> 2, tg = lane & 3;
    int wm = (wid >> 2) * 64;
    int wn = (wid & 3) * 64;

    int rowBase = blockIdx.x * 128;
    int colBase = blockIdx.y * 256;
    int NC = 3 * KC;

    int ar = tid >> 1;
    int au = (tid & 1) * 4;
    bool avalid = (rowBase + ar) < M;
    const char* Arow = (const char*)(A2 + (size_t)(rowBase + ar) * lda2);
    const char* Brow = (const char*)(B2 + (size_t)(colBase + tid) * lda2);

    auto load_chunk = [&](int c, int bb) {
        int cA = (c < KC) ? c : c - KC;          // [hi|hi|lo]
        int cB = (c < 2 * KC) ? c : c - 2 * KC;  // [hi|lo|hi]
        uint32_t pA = sbase + bb * 16384;
        uint32_t pB = sbase + 32768 + bb * 32768;
        #pragma unroll
        for (int j = 0; j < 4; j++)
            cp_async16(pA + SMEM_SWIZZLE_128B(ar * 128 + (au + j) * 16),
                       Arow + (size_t)cA * 128 + (au + j) * 16, avalid);
        #pragma unroll
        for (int j = 0; j < 8; j++)
            cp_async16(pB + SMEM_SWIZZLE_128B(tid * 128 + j * 16),
                       Brow + (size_t)cB * 128 + j * 16, true);
    };

    float acc[4][8][4];
    #pragma unroll
    for (int mt = 0; mt < 4; mt++)
        #pragma unroll
        for (int nt = 0; nt < 8; nt++)
            #pragma unroll
            for (int i = 0; i < 4; i++) acc[mt][nt][i] = 0.f;

    load_chunk(0, 0); cp_commit();
    load_chunk(1, 1); cp_commit();
    cp_wait<1>();
    __syncthreads();

    // per-lane ldmatrix addressing
    uint32_t l15 = (uint32_t)(lane & 15);
    uint32_t lx  = (uint32_t)((lane & 7) << 4);
    uint32_t hi  = (uint32_t)(lane & 16);
    uint32_t aRowOff = (uint32_t)(wm + l15) * 128;
    uint32_t bRowOff = (uint32_t)(wn + l15) * 128;

    for (int c = 0; c < NC; c++) {
        int bb = c & 1;
        uint32_t aB = sbase + bb * 16384 + aRowOff;
        uint32_t bB = sbase + 32768 + bb * 32768 + bRowOff;
        #pragma unroll
        for (int ks = 0; ks < 4; ks++) {
            uint32_t colp = ((uint32_t)(ks * 32) + hi) ^ lx;
            uint32_t a[4][4];
            #pragma unroll
            for (int mt = 0; mt < 4; mt++)
                ldsm4(a[mt][0], a[mt][1], a[mt][2], a[mt][3], aB + mt * 2048 + colp);
            #pragma unroll
            for (int ntp = 0; ntp < 4; ntp++) {
                uint32_t b0e, b0o, b1e, b1o;
                ldsm4(b0e, b0o, b1e, b1o, bB + ntp * 2048 + colp);
                #pragma unroll
                for (int mt = 0; mt < 4; mt++) {
                    mma16816(acc[mt][2 * ntp],     a[mt], b0e, b1e);
                    mma16816(acc[mt][2 * ntp + 1], a[mt], b0o, b1o);
                }
            }
        }
        __syncthreads();
        if (c + 2 < NC) {
            load_chunk(c + 2, bb); cp_commit();
            cp_wait<1>();
        } else {
            cp_wait<0>();
        }
        __syncthreads();
    }

    // epilogue
    #pragma unroll
    for (int mt = 0; mt < 4; mt++) {
        #pragma unroll
        for (int half = 0; half < 2; half++) {
            int row = rowBase + wm + mt * 16 + g + half * 8;
            if (row >= M) continue;
            #pragma unroll
            for (int nt = 0; nt < 8; nt++) {
                int col = wn + nt * 8 + tg * 2;
                int gcol = colBase + col;
                float v0 = acc[mt][nt][half * 2 + 0];
                float v1 = acc[mt][nt][half * 2 + 1];
                float2 bv = *(const float2*)(bias + gcol);
                v0 += bv.x; v1 += bv.y;
                if (resid) {
                    float2 rv = *(const float2*)(resid + (size_t)row * 256 + gcol);
                    v0 += rv.x; v1 += rv.y;
                }
                if (Cf)
                    *(float2*)(Cf + (size_t)row * ldc + gcol) = make_float2(v0, v1);
                if (Cb) {
                    __nv_bfloat16 h0, l0, h1x, l1x;
                    split_bf16(v0, h0, l0); split_bf16(v1, h1x, l1x);
                    __nv_bfloat16* o = Cb + (size_t)row * bld + bofs + gcol;
                    *(__nv_bfloat162*)(o) = __halves2bfloat162(h0, h1x);
                    *(__nv_bfloat162*)(o + bseg) = __halves2bfloat162(l0, l1x);
                }
            }
        }
    }
}

// ================= launch =================
extern "C" void kernel_launch(void* const* d_in, const int* in_sizes, int n_in,
                              void* d_out, int out_size) {
    const float* x       = (const float*)d_in[0];
    const int*   ei      = (const int*)d_in[1];
    const float* ea      = (const float*)d_in[2];
    const float* gn_e1_g = (const float*)d_in[3];
    const float* gn_e1_b = (const float*)d_in[4];
    const float* We1     = (const float*)d_in[5];
    const float* be1     = (const float*)d_in[6];
    const float* gn_e2_g = (const float*)d_in[7];
    const float* gn_e2_b = (const float*)d_in[8];
    const float* We2     = (const float*)d_in[9];
    const float* be2     = (const float*)d_in[10];
    const float* gn_n_g  = (const float*)d_in[11];
    const float* gn_n_b  = (const float*)d_in[12];
    const float* Wq      = (const float*)d_in[13];
    const float* bq      = (const float*)d_in[14];
    const float* Wk      = (const float*)d_in[15];
    const float* bk      = (const float*)d_in[16];
    const float* Wv      = (const float*)d_in[17];
    const float* bv      = (const float*)d_in[18];
    const float* Wo      = (const float*)d_in[19];
    const float* bo      = (const float*)d_in[20];
    const float* Wn1     = (const float*)d_in[21];
    const float* bn1     = (const float*)d_in[22];
    const float* gn_n2_g = (const float*)d_in[23];
    const float* gn_n2_b = (const float*)d_in[24];
    const float* Wn2     = (const float*)d_in[25];
    const float* bn2     = (const float*)d_in[26];

    const int N = in_sizes[0] / 256;
    const int E = in_sizes[2] / 256;

    __nv_bfloat16 *ein2, *h1b, *eoutb, *xb, *gattb, *cat2, *h2b;
    __nv_bfloat16 *We1t, *We2t, *Wqt, *Wkvt, *Wot, *Wn1t, *Wn2t;
    float *h1, *qb, *kvb, *attbuf, *h2, *bkv;
    cudaGetSymbolAddress((void**)&ein2,   g_ein2);
    cudaGetSymbolAddress((void**)&h1,     g_h1);
    cudaGetSymbolAddress((void**)&h1b,    g_h1b);
    cudaGetSymbolAddress((void**)&eoutb,  g_eoutb);
    cudaGetSymbolAddress((void**)&xb,     g_xb);
    cudaGetSymbolAddress((void**)&qb,     g_q);
    cudaGetSymbolAddress((void**)&kvb,    g_kv);
    cudaGetSymbolAddress((void**)&attbuf, g_attbuf);
    cudaGetSymbolAddress((void**)&gattb,  g_gattb);
    cudaGetSymbolAddress((void**)&cat2,   g_cat2);
    cudaGetSymbolAddress((void**)&h2,     g_h2);
    cudaGetSymbolAddress((void**)&h2b,    g_h2b);
    cudaGetSymbolAddress((void**)&bkv,    g_bkv);
    cudaGetSymbolAddress((void**)&We1t,   g_We1t);
    cudaGetSymbolAddress((void**)&We2t,   g_We2t);
    cudaGetSymbolAddress((void**)&Wqt,    g_Wqt);
    cudaGetSymbolAddress((void**)&Wkvt,   g_Wkvt);
    cudaGetSymbolAddress((void**)&Wot,    g_Wot);
    cudaGetSymbolAddress((void**)&Wn1t,   g_Wn1t);
    cudaGetSymbolAddress((void**)&Wn2t,   g_Wn2t);

    float* n_out = (float*)d_out;
    float* e_out = (float*)d_out + (size_t)N * 256;
    float* gatt   = attbuf;
    float* expsum = attbuf + (size_t)N * 256;
    float* vsum   = expsum + (size_t)N * 4;

    const int DSMEM = 98304 + 1024;
    cudaFuncSetAttribute(tc_gemm_kernel, cudaFuncAttributeMaxDynamicSharedMemorySize, DSMEM);

    int gemmE = (E + 127) / 128;
    int gemmN = (N + 127) / 128;

    // 0: all weight preps in one launch
    WPA wpa;
    wpa.W[0] = We1; wpa.O[0] = We1t;           wpa.K[0] = 768;
    wpa.W[1] = We2; wpa.O[1] = We2t;           wpa.K[1] = 256;
    wpa.W[2] = Wq;  wpa.O[2] = Wqt;            wpa.K[2] = 256;
    wpa.W[3] = Wk;  wpa.O[3] = Wkvt;           wpa.K[3] = 256;
    wpa.W[4] = Wv;  wpa.O[4] = Wkvt + 256*512; wpa.K[4] = 256;
    wpa.W[5] = Wo;  wpa.O[5] = Wot;            wpa.K[5] = 256;
    wpa.W[6] = Wn1; wpa.O[6] = Wn1t;           wpa.K[6] = 512;
    wpa.W[7] = Wn2; wpa.O[7] = Wn2t;           wpa.K[7] = 256;
    int acc0 = 0;
    for (int i = 0; i < 8; i++) { wpa.start[i] = acc0; acc0 += wpa.K[i]; }
    wpa.start[8] = acc0;
    wprep_all_kernel<<<acc0, 256>>>(wpa);

    // 1: xprep + zero + bkv
    int zcount = N * 256 + N * 4 + 256;
    int miscTot = N * 256 + zcount + 512;
    misc_prep_kernel<<<(miscTot + 255) / 256, 256>>>(x, xb, attbuf, zcount, bk, bv, bkv, N);

    // 2: edge input GN
    gn_edge2_kernel<<<E, 256>>>(x, ei, ea, gn_e1_g, gn_e1_b, ein2, E);
    // 3: h1 = ein @ We1
    tc_gemm_kernel<<<dim3(gemmE, 1), 256, DSMEM>>>(ein2, 1536, 12, We1t, be1, nullptr,
                                                   h1, 256, nullptr, 0, 0, 0, E);
    // 4: GN -> h1b
    gn256b_kernel<<<(E + 7) / 8, 256>>>(h1, gn_e2_g, gn_e2_b, h1b, 512, 0, 256, E);
    // 5: e_out = h1b @ We2 + ea   [PROFILED LAUNCH]
    tc_gemm_kernel<<<dim3(gemmE, 1), 256, DSMEM>>>(h1b, 512, 4, We2t, be2, ea,
                                                   e_out, 256, eoutb, 512, 0, 256, E);
    // 6: q = x @ Wq
    tc_gemm_kernel<<<dim3(gemmN, 1), 256, DSMEM>>>(xb, 512, 4, Wqt, bq, nullptr,
                                                   qb, 256, nullptr, 0, 0, 0, N);
    // 7: kv = e_out @ [Wk|Wv]  (col-tiled)
    tc_gemm_kernel<<<dim3(gemmE, 2), 256, DSMEM>>>(eoutb, 512, 4, Wkvt, bkv, nullptr,
                                                   kvb, 512, nullptr, 0, 0, 0, E);
    // 8-10: sparse attention
    colsum_kernel<<<64, 256>>>(kvb, vsum, E);
    attn_scatter_kernel<<<E, 256>>>(qb, kvb, ei, expsum, gatt, E);
    attn_finalize2_kernel<<<N, 256>>>(gatt, expsum, vsum, 1.0f / (float)E, gattb);
    // 11: g_o = gatt @ Wo -> cat right half
    tc_gemm_kernel<<<dim3(gemmN, 1), 256, DSMEM>>>(gattb, 512, 4, Wot, bo, nullptr,
                                                   nullptr, 0, cat2, 1024, 256, 512, N);
    // 12: xa = GN(x) -> cat left half
    gn256b_kernel<<<(N + 7) / 8, 256>>>(x, gn_n_g, gn_n_b, cat2, 1024, 0, 512, N);
    // 13: h2 = cat @ Wn1
    tc_gemm_kernel<<<dim3(gemmN, 1), 256, DSMEM>>>(cat2, 1024, 8, Wn1t, bn1, nullptr,
                                                   h2, 256, nullptr, 0, 0, 0, N);
    // 14: GN -> h2b
    gn256b_kernel<<<(N + 7) / 8, 256>>>(h2, gn_n2_g, gn_n2_b, h2b, 512, 0, 256, N);
    // 15: n_out = h2b @ Wn2 + x
    tc_gemm_kernel<<<dim3(gemmN, 1), 256, DSMEM>>>(h2b, 512, 4, Wn2t, bn2, x,
                                                   n_out, 256, nullptr, 0, 0, 0, N);
}

// round 6
// speedup vs baseline: 1.1053x; 1.0198x over previous
#include <cuda_runtime.h>
#include <cuda_bf16.h>
#include <cstdint>
#include <cstddef>

// ================= problem constants =================
#define MAX_E 16000
#define MAX_N 2000
// CH=256, HID=256, 3CH=768, HEADS=4, dk=64

// ================= helpers =================
__device__ __forceinline__ uint32_t smem_to_u32(const void* smem_ptr) {
    uint32_t addr;
    asm("{ .reg .u64 tmp; cvta.to.shared.u64 tmp, %1; cvt.u32.u64 %0, tmp; }"
        : "=r"(addr) : "l"(smem_ptr));
    return addr;
}
#define SMEM_SWIZZLE_128B(byte_offset) ((byte_offset) ^ (((byte_offset) >> 3) & 0x70))

__device__ __forceinline__ void cp_async16(uint32_t dst, const void* src, bool valid) {
    int sz = valid ? 16 : 0;
    asm volatile("cp.async.cg.shared.global [%0], [%1], 16, %2;"
                 :: "r"(dst), "l"(src), "r"(sz) : "memory");
}
__device__ __forceinline__ void cp_commit() {
    asm volatile("cp.async.commit_group;" ::: "memory");
}
template <int N>
__device__ __forceinline__ void cp_wait() {
    asm volatile("cp.async.wait_group %0;" :: "n"(N) : "memory");
}
__device__ __forceinline__ void ldsm4(uint32_t& r0, uint32_t& r1, uint32_t& r2, uint32_t& r3,
                                      uint32_t addr) {
    asm volatile("ldmatrix.sync.aligned.m8n8.x4.shared.b16 {%0,%1,%2,%3}, [%4];"
                 : "=r"(r0), "=r"(r1), "=r"(r2), "=r"(r3) : "r"(addr));
}
__device__ __forceinline__ void mma16816(float* c, const uint32_t* a, uint32_t b0, uint32_t b1) {
    asm volatile(
        "mma.sync.aligned.m16n8k16.row.col.f32.bf16.bf16.f32 "
        "{%0,%1,%2,%3}, {%4,%5,%6,%7}, {%8,%9}, {%0,%1,%2,%3};"
        : "+f"(c[0]), "+f"(c[1]), "+f"(c[2]), "+f"(c[3])
        : "r"(a[0]), "r"(a[1]), "r"(a[2]), "r"(a[3]), "r"(b0), "r"(b1));
}
__device__ __forceinline__ void split_bf16(float v, __nv_bfloat16& h, __nv_bfloat16& l) {
    h = __float2bfloat16(v);
    l = __float2bfloat16(v - __bfloat162float(h));
}

// ================= scratch =================
__device__ __align__(256) __nv_bfloat16 g_ein2[(size_t)MAX_E * 1536];
__device__ __align__(256) float         g_h1[(size_t)MAX_E * 256];
__device__ __align__(256) __nv_bfloat16 g_h1b[(size_t)MAX_E * 512];
__device__ __align__(256) __nv_bfloat16 g_eoutb[(size_t)MAX_E * 512];
__device__ __align__(256) __nv_bfloat16 g_xb[(size_t)MAX_N * 512];
__device__ __align__(256) float         g_q[(size_t)MAX_N * 256];
__device__ __align__(256) float         g_kv[(size_t)MAX_E * 512];
__device__ __align__(256) float         g_attbuf[(size_t)MAX_N * 256 + MAX_N * 4 + 256];
__device__ __align__(256) __nv_bfloat16 g_gattb[(size_t)MAX_N * 512];
__device__ __align__(256) __nv_bfloat16 g_cat2[(size_t)MAX_N * 1024];
__device__ __align__(256) float         g_h2[(size_t)MAX_N * 256];
__device__ __align__(256) __nv_bfloat16 g_h2b[(size_t)MAX_N * 512];
__device__ __align__(256) float         g_bkv[512];
// 2-seg transposed weights [Ncols, 2K] = [hi | lo]
__device__ __align__(256) __nv_bfloat16 g_We1t[256 * 1536];
__device__ __align__(256) __nv_bfloat16 g_We2t[256 * 512];
__device__ __align__(256) __nv_bfloat16 g_Wqt[256 * 512];
__device__ __align__(256) __nv_bfloat16 g_Wkvt[512 * 512];
__device__ __align__(256) __nv_bfloat16 g_Wot[256 * 512];
__device__ __align__(256) __nv_bfloat16 g_Wn1t[256 * 1024];
__device__ __align__(256) __nv_bfloat16 g_Wn2t[256 * 512];

// ================= fused prep =================
struct WPA {
    const float* W[8];
    __nv_bfloat16* O[8];
    int K[8];
    int start[9];
};
__global__ void wprep_all_kernel(WPA a) {
    int b = blockIdx.x;
    int i = 0;
    #pragma unroll
    for (int j = 1; j < 8; j++) if (b >= a.start[j]) i = j;
    int k = b - a.start[i];
    int K = a.K[i];
    int col = threadIdx.x;
    float v = a.W[i][(size_t)k * 256 + col];
    __nv_bfloat16 h, l; split_bf16(v, h, l);
    a.O[i][(size_t)col * 2 * K + k] = h;
    a.O[i][(size_t)col * 2 * K + K + k] = l;
}

__global__ void misc_prep_kernel(const float* __restrict__ x, __nv_bfloat16* __restrict__ xb,
                                 float* __restrict__ attbuf, int zcount,
                                 const float* __restrict__ bk, const float* __restrict__ bv,
                                 float* __restrict__ bkv, int M) {
    int idx = blockIdx.x * blockDim.x + threadIdx.x;
    if (idx < M * 256) {
        int r = idx >> 8, c = idx & 255;
        float v = x[idx];
        __nv_bfloat16 h, l; split_bf16(v, h, l);
        xb[(size_t)r * 512 + c] = h;
        xb[(size_t)r * 512 + 256 + c] = l;
    }
    int z = idx - M * 256;
    if (z >= 0 && z < zcount) attbuf[z] = 0.f;
    int bidx = idx - M * 256 - zcount;
    if (bidx >= 0 && bidx < 512)
        bkv[bidx] = (bidx < 256) ? bk[bidx] : bv[bidx - 256];
}

__global__ void gn_edge2_kernel(const float* __restrict__ x, const int* __restrict__ ei,
                                const float* __restrict__ ea,
                                const float* __restrict__ gamma, const float* __restrict__ beta,
                                __nv_bfloat16* __restrict__ out, int E) {
    __shared__ float buf[768];
    __shared__ float s_mu[32], s_rs[32];
    int e = blockIdx.x;
    int t = threadIdx.x;
    int r = ei[e];
    int c = ei[E + e];
    buf[t]       = x[(size_t)r * 256 + t];
    buf[256 + t] = x[(size_t)c * 256 + t];
    buf[512 + t] = ea[(size_t)e * 256 + t];
    __syncthreads();
    if (t < 32) {
        float s = 0.f, s2 = 0.f;
        #pragma unroll
        for (int i = 0; i < 24; i++) { float v = buf[t * 24 + i]; s += v; s2 += v * v; }
        float m = s * (1.f / 24.f);
        float var = s2 * (1.f / 24.f) - m * m;
        s_mu[t] = m; s_rs[t] = rsqrtf(var + 1e-5f);
    }
    __syncthreads();
    size_t base = (size_t)e * 1536;
    #pragma unroll
    for (int i = t; i < 768; i += 256) {
        int grp = i / 24;
        float v = fmaxf((buf[i] - s_mu[grp]) * s_rs[grp] * gamma[i] + beta[i], 0.f);
        __nv_bfloat16 h, l; split_bf16(v, h, l);
        out[base + i] = h;
        out[base + 768 + i] = l;
    }
}

__global__ void gn256b_kernel(const float* __restrict__ in, const float* __restrict__ gamma,
                              const float* __restrict__ beta, __nv_bfloat16* __restrict__ out,
                              int bld, int bofs, int bseg, int M) {
    int t = threadIdx.x;
    int row = blockIdx.x * 8 + (t >> 5);
    if (row >= M) return;
    int g = t & 31;
    const float* p = in + (size_t)row * 256 + g * 8;
    float4 a = *(const float4*)p;
    float4 b = *(const float4*)(p + 4);
    float s = a.x + a.y + a.z + a.w + b.x + b.y + b.z + b.w;
    float s2 = a.x*a.x + a.y*a.y + a.z*a.z + a.w*a.w + b.x*b.x + b.y*b.y + b.z*b.z + b.w*b.w;
    float m = s * 0.125f;
    float var = s2 * 0.125f - m * m;
    float rs = rsqrtf(var + 1e-5f);
    float vals[8] = {a.x, a.y, a.z, a.w, b.x, b.y, b.z, b.w};
    __nv_bfloat16 hs[8], ls[8];
    #pragma unroll
    for (int i = 0; i < 8; i++) {
        int ch = g * 8 + i;
        float v = fmaxf((vals[i] - m) * rs * gamma[ch] + beta[ch], 0.f);
        split_bf16(v, hs[i], ls[i]);
    }
    __nv_bfloat16* o = out + (size_t)row * bld + bofs + g * 8;
    #pragma unroll
    for (int i = 0; i < 4; i++) {
        *(__nv_bfloat162*)(o + 2*i) = __halves2bfloat162(hs[2*i], hs[2*i+1]);
        *(__nv_bfloat162*)(o + bseg + 2*i) = __halves2bfloat162(ls[2*i], ls[2*i+1]);
    }
}

__global__ void colsum_kernel(const float* __restrict__ kv, float* __restrict__ vsum, int E) {
    int t = threadIdx.x;
    float s = 0.f;
    for (int e = blockIdx.x; e < E; e += gridDim.x)
        s += kv[(size_t)e * 512 + 256 + t];
    atomicAdd(&vsum[t], s);
}

__global__ void attn_scatter_kernel(const float* __restrict__ q, const float* __restrict__ kv,
                                    const int* __restrict__ ei,
                                    float* __restrict__ expsum, float* __restrict__ gatt, int E) {
    __shared__ float wsum[8];
    __shared__ float wexp[4];
    int e = blockIdx.x;
    int t = threadIdx.x;
    int n = ei[E + e];
    float p = q[(size_t)n * 256 + t] * kv[(size_t)e * 512 + t];
    #pragma unroll
    for (int off = 16; off >= 1; off >>= 1)
        p += __shfl_xor_sync(0xffffffffu, p, off);
    int warp = t >> 5, lane = t & 31;
    if (lane == 0) wsum[warp] = p;
    __syncthreads();
    if (t < 4) {
        float s = (wsum[2 * t] + wsum[2 * t + 1]) * 0.125f;
        float w = expf(s);
        wexp[t] = w;
        atomicAdd(&expsum[n * 4 + t], w);
    }
    __syncthreads();
    float w = wexp[t >> 6];
    atomicAdd(&gatt[(size_t)n * 256 + t], w * kv[(size_t)e * 512 + 256 + t]);
}

__global__ void attn_finalize2_kernel(const float* __restrict__ gatt, const float* __restrict__ expsum,
                                      const float* __restrict__ vsum, float invE,
                                      __nv_bfloat16* __restrict__ out) {
    int n = blockIdx.x, t = threadIdx.x;
    float es = expsum[n * 4 + (t >> 6)];
    float val = (es > 0.f) ? gatt[(size_t)n * 256 + t] / es : vsum[t] * invE;
    __nv_bfloat16 h, l; split_bf16(val, h, l);
    size_t base = (size_t)n * 512;
    out[base + t] = h;
    out[base + 256 + t] = l;
}

// ================= mma.sync GEMM =================
// CTA tile: 64 rows x 256 cols. 8 warps in 2x4, warp tile 32x64.
// K chunks of 64 bf16 (128B), double buffered. Target 2 CTAs/SM.
// A physical [M,2K]=[hi|lo] -> logical [hi|hi|lo]; B physical [Ncols,2K]=[hi|lo] -> [hi|lo|hi]
__global__ void __launch_bounds__(256, 2) tc_gemm_kernel(
    const __nv_bfloat16* __restrict__ A2, int lda2, int KC,
    const __nv_bfloat16* __restrict__ B2,
    const float* __restrict__ bias,
    const float* __restrict__ resid,
    float* __restrict__ Cf, int ldc,
    __nv_bfloat16* __restrict__ Cb, int bld, int bofs, int bseg,
    int M)
{
    extern __shared__ char smem_raw[];
    char* smem = (char*)(((uintptr_t)smem_raw + 1023) & ~(uintptr_t)1023);
    uint32_t sbase = smem_to_u32(smem);

    int tid = threadIdx.x;
    int wid = tid >> 5;
    int lane = tid & 31;
    int g = lane >> 2, tg = lane & 3;
    int wm = (wid >> 2) * 32;       // 0 or 32
    int wn = (wid & 3) * 64;        // 0,64,128,192

    int rowBase = blockIdx.x * 64;
    int colBase = blockIdx.y * 256;
    int NC = 3 * KC;

    // A loader: 64 rows x 8 u4-groups = 512 loads, 2/thread
    int ar = tid >> 2;
    int au = (tid & 3) * 2;
    bool avalid = (rowBase + ar) < M;
    const char* Arow = (const char*)(A2 + (size_t)(rowBase + ar) * lda2);
    const char* Brow = (const char*)(B2 + (size_t)(colBase + tid) * lda2);

    auto load_chunk = [&](int c, int bb) {
        int cA = (c < KC) ? c : c - KC;
        int cB = (c < 2 * KC) ? c : c - 2 * KC;
        uint32_t pA = sbase + bb * 8192;
        uint32_t pB = sbase + 16384 + bb * 32768;
        #pragma unroll
        for (int j = 0; j < 2; j++)
            cp_async16(pA + SMEM_SWIZZLE_128B(ar * 128 + (au + j) * 16),
                       Arow + (size_t)cA * 128 + (au + j) * 16, avalid);
        #pragma unroll
        for (int j = 0; j < 8; j++)
            cp_async16(pB + SMEM_SWIZZLE_128B(tid * 128 + j * 16),
                       Brow + (size_t)cB * 128 + j * 16, true);
    };

    float acc[2][8][4];
    #pragma unroll
    for (int mt = 0; mt < 2; mt++)
        #pragma unroll
        for (int nt = 0; nt < 8; nt++)
            #pragma unroll
            for (int i = 0; i < 4; i++) acc[mt][nt][i] = 0.f;

    load_chunk(0, 0); cp_commit();
    load_chunk(1, 1); cp_commit();
    cp_wait<1>();
    __syncthreads();

    uint32_t l15 = (uint32_t)(lane & 15);
    uint32_t lx  = (uint32_t)((lane & 7) << 4);
    uint32_t hi  = (uint32_t)(lane & 16);
    uint32_t aRowOff = (uint32_t)(wm + l15) * 128;
    uint32_t bRowOff = (uint32_t)(wn + l15) * 128;

    for (int c = 0; c < NC; c++) {
        int bb = c & 1;
        uint32_t aB = sbase + bb * 8192 + aRowOff;
        uint32_t bB = sbase + 16384 + bb * 32768 + bRowOff;
        #pragma unroll
        for (int ks = 0; ks < 4; ks++) {
            uint32_t colp = ((uint32_t)(ks * 32) + hi) ^ lx;
            uint32_t a[2][4];
            #pragma unroll
            for (int mt = 0; mt < 2; mt++)
                ldsm4(a[mt][0], a[mt][1], a[mt][2], a[mt][3], aB + mt * 2048 + colp);
            #pragma unroll
            for (int ntp = 0; ntp < 4; ntp++) {
                uint32_t b0e, b0o, b1e, b1o;
                ldsm4(b0e, b0o, b1e, b1o, bB + ntp * 2048 + colp);
                #pragma unroll
                for (int mt = 0; mt < 2; mt++) {
                    mma16816(acc[mt][2 * ntp],     a[mt], b0e, b1e);
                    mma16816(acc[mt][2 * ntp + 1], a[mt], b0o, b1o);
                }
            }
        }
        __syncthreads();
        if (c + 2 < NC) {
            load_chunk(c + 2, bb); cp_commit();
            cp_wait<1>();
        } else {
            cp_wait<0>();
        }
        __syncthreads();
    }

    // epilogue
    #pragma unroll
    for (int mt = 0; mt < 2; mt++) {
        #pragma unroll
        for (int half = 0; half < 2; half++) {
            int row = rowBase + wm + mt * 16 + g + half * 8;
            if (row >= M) continue;
            #pragma unroll
            for (int nt = 0; nt < 8; nt++) {
                int col = wn + nt * 8 + tg * 2;
                int gcol = colBase + col;
                float v0 = acc[mt][nt][half * 2 + 0];
                float v1 = acc[mt][nt][half * 2 + 1];
                float2 bv = *(const float2*)(bias + gcol);
                v0 += bv.x; v1 += bv.y;
                if (resid) {
                    float2 rv = *(const float2*)(resid + (size_t)row * 256 + gcol);
                    v0 += rv.x; v1 += rv.y;
                }
                if (Cf)
                    *(float2*)(Cf + (size_t)row * ldc + gcol) = make_float2(v0, v1);
                if (Cb) {
                    __nv_bfloat16 h0, l0, h1x, l1x;
                    split_bf16(v0, h0, l0); split_bf16(v1, h1x, l1x);
                    __nv_bfloat16* o = Cb + (size_t)row * bld + bofs + gcol;
                    *(__nv_bfloat162*)(o) = __halves2bfloat162(h0, h1x);
                    *(__nv_bfloat162*)(o + bseg) = __halves2bfloat162(l0, l1x);
                }
            }
        }
    }
}

// ================= launch =================
extern "C" void kernel_launch(void* const* d_in, const int* in_sizes, int n_in,
                              void* d_out, int out_size) {
    const float* x       = (const float*)d_in[0];
    const int*   ei      = (const int*)d_in[1];
    const float* ea      = (const float*)d_in[2];
    const float* gn_e1_g = (const float*)d_in[3];
    const float* gn_e1_b = (const float*)d_in[4];
    const float* We1     = (const float*)d_in[5];
    const float* be1     = (const float*)d_in[6];
    const float* gn_e2_g = (const float*)d_in[7];
    const float* gn_e2_b = (const float*)d_in[8];
    const float* We2     = (const float*)d_in[9];
    const float* be2     = (const float*)d_in[10];
    const float* gn_n_g  = (const float*)d_in[11];
    const float* gn_n_b  = (const float*)d_in[12];
    const float* Wq      = (const float*)d_in[13];
    const float* bq      = (const float*)d_in[14];
    const float* Wk      = (const float*)d_in[15];
    const float* bk      = (const float*)d_in[16];
    const float* Wv      = (const float*)d_in[17];
    const float* bv      = (const float*)d_in[18];
    const float* Wo      = (const float*)d_in[19];
    const float* bo      = (const float*)d_in[20];
    const float* Wn1     = (const float*)d_in[21];
    const float* bn1     = (const float*)d_in[22];
    const float* gn_n2_g = (const float*)d_in[23];
    const float* gn_n2_b = (const float*)d_in[24];
    const float* Wn2     = (const float*)d_in[25];
    const float* bn2     = (const float*)d_in[26];

    const int N = in_sizes[0] / 256;
    const int E = in_sizes[2] / 256;

    __nv_bfloat16 *ein2, *h1b, *eoutb, *xb, *gattb, *cat2, *h2b;
    __nv_bfloat16 *We1t, *We2t, *Wqt, *Wkvt, *Wot, *Wn1t, *Wn2t;
    float *h1, *qb, *kvb, *attbuf, *h2, *bkv;
    cudaGetSymbolAddress((void**)&ein2,   g_ein2);
    cudaGetSymbolAddress((void**)&h1,     g_h1);
    cudaGetSymbolAddress((void**)&h1b,    g_h1b);
    cudaGetSymbolAddress((void**)&eoutb,  g_eoutb);
    cudaGetSymbolAddress((void**)&xb,     g_xb);
    cudaGetSymbolAddress((void**)&qb,     g_q);
    cudaGetSymbolAddress((void**)&kvb,    g_kv);
    cudaGetSymbolAddress((void**)&attbuf, g_attbuf);
    cudaGetSymbolAddress((void**)&gattb,  g_gattb);
    cudaGetSymbolAddress((void**)&cat2,   g_cat2);
    cudaGetSymbolAddress((void**)&h2,     g_h2);
    cudaGetSymbolAddress((void**)&h2b,    g_h2b);
    cudaGetSymbolAddress((void**)&bkv,    g_bkv);
    cudaGetSymbolAddress((void**)&We1t,   g_We1t);
    cudaGetSymbolAddress((void**)&We2t,   g_We2t);
    cudaGetSymbolAddress((void**)&Wqt,    g_Wqt);
    cudaGetSymbolAddress((void**)&Wkvt,   g_Wkvt);
    cudaGetSymbolAddress((void**)&Wot,    g_Wot);
    cudaGetSymbolAddress((void**)&Wn1t,   g_Wn1t);
    cudaGetSymbolAddress((void**)&Wn2t,   g_Wn2t);

    float* n_out = (float*)d_out;
    float* e_out = (float*)d_out + (size_t)N * 256;
    float* gatt   = attbuf;
    float* expsum = attbuf + (size_t)N * 256;
    float* vsum   = expsum + (size_t)N * 4;

    const int DSMEM = 81920 + 1024;
    cudaFuncSetAttribute(tc_gemm_kernel, cudaFuncAttributeMaxDynamicSharedMemorySize, DSMEM);

    int gemmE = (E + 63) / 64;
    int gemmN = (N + 63) / 64;

    WPA wpa;
    wpa.W[0] = We1; wpa.O[0] = We1t;           wpa.K[0] = 768;
    wpa.W[1] = We2; wpa.O[1] = We2t;           wpa.K[1] = 256;
    wpa.W[2] = Wq;  wpa.O[2] = Wqt;            wpa.K[2] = 256;
    wpa.W[3] = Wk;  wpa.O[3] = Wkvt;           wpa.K[3] = 256;
    wpa.W[4] = Wv;  wpa.O[4] = Wkvt + 256*512; wpa.K[4] = 256;
    wpa.W[5] = Wo;  wpa.O[5] = Wot;            wpa.K[5] = 256;
    wpa.W[6] = Wn1; wpa.O[6] = Wn1t;           wpa.K[6] = 512;
    wpa.W[7] = Wn2; wpa.O[7] = Wn2t;           wpa.K[7] = 256;
    int acc0 = 0;
    for (int i = 0; i < 8; i++) { wpa.start[i] = acc0; acc0 += wpa.K[i]; }
    wpa.start[8] = acc0;
    wprep_all_kernel<<<acc0, 256>>>(wpa);

    int zcount = N * 256 + N * 4 + 256;
    int miscTot = N * 256 + zcount + 512;
    misc_prep_kernel<<<(miscTot + 255) / 256, 256>>>(x, xb, attbuf, zcount, bk, bv, bkv, N);

    gn_edge2_kernel<<<E, 256>>>(x, ei, ea, gn_e1_g, gn_e1_b, ein2, E);
    tc_gemm_kernel<<<dim3(gemmE, 1), 256, DSMEM>>>(ein2, 1536, 12, We1t, be1, nullptr,
                                                   h1, 256, nullptr, 0, 0, 0, E);
    gn256b_kernel<<<(E + 7) / 8, 256>>>(h1, gn_e2_g, gn_e2_b, h1b, 512, 0, 256, E);
    // [PROFILED LAUNCH index 5]
    tc_gemm_kernel<<<dim3(gemmE, 1), 256, DSMEM>>>(h1b, 512, 4, We2t, be2, ea,
                                                   e_out, 256, eoutb, 512, 0, 256, E);
    tc_gemm_kernel<<<dim3(gemmN, 1), 256, DSMEM>>>(xb, 512, 4, Wqt, bq, nullptr,
                                                   qb, 256, nullptr, 0, 0, 0, N);
    tc_gemm_kernel<<<dim3(gemmE, 2), 256, DSMEM>>>(eoutb, 512, 4, Wkvt, bkv, nullptr,
                                                   kvb, 512, nullptr, 0, 0, 0, E);
    colsum_kernel<<<64, 256>>>(kvb, vsum, E);
    attn_scatter_kernel<<<E, 256>>>(qb, kvb, ei, expsum, gatt, E);
    attn_finalize2_kernel<<<N, 256>>>(gatt, expsum, vsum, 1.0f / (float)E, gattb);
    tc_gemm_kernel<<<dim3(gemmN, 1), 256, DSMEM>>>(gattb, 512, 4, Wot, bo, nullptr,
                                                   nullptr, 0, cat2, 1024, 256, 512, N);
    gn256b_kernel<<<(N + 7) / 8, 256>>>(x, gn_n_g, gn_n_b, cat2, 1024, 0, 512, N);
    tc_gemm_kernel<<<dim3(gemmN, 1), 256, DSMEM>>>(cat2, 1024, 8, Wn1t, bn1, nullptr,
                                                   h2, 256, nullptr, 0, 0, 0, N);
    gn256b_kernel<<<(N + 7) / 8, 256>>>(h2, gn_n2_g, gn_n2_b, h2b, 512, 0, 256, N);
    tc_gemm_kernel<<<dim3(gemmN, 1), 256, DSMEM>>>(h2b, 512, 4, Wn2t, bn2, x,
                                                   n_out, 256, nullptr, 0, 0, 0, N);
}